// round 4
// baseline (speedup 1.0000x reference)
#include <cuda_runtime.h>

#define N_   8
#define D_   64
#define H_   64
#define W_   64
#define HW_  4096
#define CHW  (D_*HW_)   /* 262144 */
#define KK   25

// Scratch (static __device__ allocation — allowed; no runtime allocs)
__device__ int   g_cnt[2][N_];
__device__ float g_inv[N_];
__device__ float g_w[N_*HW_*KK];   // per-pixel normalized window weights (delta at k=12 if zero_mass)

__global__ void zero_cnt_kernel() {
    int t = threadIdx.x;
    if (t < 2*N_) ((int*)g_cnt)[t] = 0;
}

// Count nonzeros of cur (arr=0) and prev (arr=1) per batch.
__global__ void count_kernel(const float* __restrict__ cur, const float* __restrict__ prev) {
    int arr = blockIdx.y;
    int n   = blockIdx.z;
    const float4* p = (const float4*)((arr == 0 ? cur : prev) + (size_t)n * CHW);
    const int nv = CHW / 4;
    int cnt = 0;
    for (int i = blockIdx.x * blockDim.x + threadIdx.x; i < nv; i += gridDim.x * blockDim.x) {
        float4 v = p[i];
        cnt += (v.x != 0.f) + (v.y != 0.f) + (v.z != 0.f) + (v.w != 0.f);
    }
    #pragma unroll
    for (int o = 16; o; o >>= 1) cnt += __shfl_xor_sync(0xffffffffu, cnt, o);
    __shared__ int ws[8];
    int lane = threadIdx.x & 31, wid = threadIdx.x >> 5;
    if (lane == 0) ws[wid] = cnt;
    __syncthreads();
    if (wid == 0) {
        int c = (lane < (int)(blockDim.x >> 5)) ? ws[lane] : 0;
        #pragma unroll
        for (int o = 4; o; o >>= 1) c += __shfl_xor_sync(0xffffffffu, c, o);
        if (lane == 0) atomicAdd(&g_cnt[arr][n], c);
    }
}

__global__ void finalize_kernel() {
    int t = threadIdx.x;
    if (t < N_) {
        float a = (float)g_cnt[0][t] + 1e-8f;
        float b = (float)g_cnt[1][t] + 1e-8f;
        g_inv[t] = 1.0f / (a * b);
    }
}

// One CTA per (row y, batch n). 512 threads: 8 threads per pixel split the 25
// taps (<=4 each); d unrolled by 4 with explicit load batching for MLP.
// smem: cur row [d][x] (16KB) + 5 clamped prev rows [r][d][x] (80KB).
__global__ __launch_bounds__(512) void weights_kernel(const float* __restrict__ cur,
                                                      const float* __restrict__ prev) {
    extern __shared__ float sm[];
    float* cur_s  = sm;          // idx = d*64 + x
    float* prev_s = sm + HW_;    // idx = r*4096 + d*64 + x  (rows clamped)
    const int y = blockIdx.x, n = blockIdx.y;
    const int t = threadIdx.x;
    const float* curb  = cur  + (size_t)n * CHW;
    const float* prevb = prev + (size_t)n * CHW;

    for (int i = t; i < HW_; i += 512)
        cur_s[i] = curb[(i >> 6) * HW_ + y * W_ + (i & 63)];
    for (int i = t; i < 5 * HW_; i += 512) {
        int r = i >> 12, rem = i & 4095;
        int yy = y - 2 + r; yy = yy < 0 ? 0 : (yy > H_-1 ? H_-1 : yy);
        prev_s[i] = prevb[(rem >> 6) * HW_ + yy * W_ + (rem & 63)];
    }
    __syncthreads();

    const int x = t >> 3, q = t & 7;   // 8 consecutive lanes share a pixel

    int   base[4];
    float live[4];
    #pragma unroll
    for (int j = 0; j < 4; j++) {
        int k  = q + 8 * j;
        int kk = k < KK ? k : 12;           // dead slot -> harmless center tap
        int dy = kk / 5 - 2, dx = kk % 5 - 2;
        int py = y + dy, px = x + dx;
        bool ok = (k < KK) && py >= 0 && py < H_ && px >= 0 && px < W_;
        int pxc = px < 0 ? 0 : (px > W_-1 ? W_-1 : px);
        base[j] = (kk / 5) * HW_ + pxc;
        live[j] = ok ? 1.0f : 0.0f;
    }

    float acc[4] = {0.f, 0.f, 0.f, 0.f};
    for (int d = 0; d < D_; d += 4) {
        float c[4], p[16];
        #pragma unroll
        for (int i = 0; i < 4; i++) c[i] = cur_s[(d + i) * 64 + x];
        #pragma unroll
        for (int j = 0; j < 4; j++)
            #pragma unroll
            for (int i = 0; i < 4; i++)
                p[j * 4 + i] = prev_s[base[j] + (d + i) * 64];
        #pragma unroll
        for (int j = 0; j < 4; j++)
            #pragma unroll
            for (int i = 0; i < 4; i++)
                acc[j] = fmaf(c[i], p[j * 4 + i], acc[j]);
    }

    float m = 0.f;
    #pragma unroll
    for (int j = 0; j < 4; j++) {
        acc[j] = fmaxf(acc[j], 0.f) * live[j];   // unscaled coef (scale cancels in w)
        m += acc[j];
    }
    m += __shfl_xor_sync(0xffffffffu, m, 1);
    m += __shfl_xor_sync(0xffffffffu, m, 2);
    m += __shfl_xor_sync(0xffffffffu, m, 4);

    const float inv  = g_inv[n];
    const bool  zero = fabsf(m * inv) < 1e-7f;   // reference threshold (scaled domain)
    const float invm = zero ? 0.f : 1.0f / m;

    const size_t wbase = ((size_t)(n * HW_ + y * W_ + x)) * KK;
    #pragma unroll
    for (int j = 0; j < 4; j++) {
        int k = q + 8 * j;
        if (k < KK) {
            float wv = zero ? (k == 12 ? 1.0f : 0.0f) : acc[j] * invm;
            g_w[wbase + k] = wv;
        }
    }
}

// One CTA per (row y, batch n). 256 threads: pixel x (64) * d-group (4 of 16).
// smem: 5 prev_mem rows (80KB) + staged weights row (6.4KB).
// 25 tap loads batched into temps, 4 independent accumulators.
__global__ __launch_bounds__(256) void output_kernel(const float* __restrict__ pm,
                                                     float* __restrict__ out) {
    extern __shared__ float sm2[];
    float* pm_s = sm2;              // [5][64][64]
    float* ws_s = sm2 + 5 * HW_;    // [64][25]
    const int y = blockIdx.x, n = blockIdx.y;
    const int t = threadIdx.x;
    const float* pmb = pm + (size_t)n * CHW;

    for (int i = t; i < 5 * HW_; i += 256) {
        int r = i >> 12, rem = i & 4095;
        int yy = y - 2 + r; yy = yy < 0 ? 0 : (yy > H_-1 ? H_-1 : yy);
        pm_s[i] = pmb[(rem >> 6) * HW_ + yy * W_ + (rem & 63)];
    }
    {
        const float* gw = g_w + ((size_t)(n * HW_ + y * W_)) * KK;
        for (int i = t; i < W_ * KK; i += 256) ws_s[i] = gw[i];
    }
    __syncthreads();

    const int x = t & 63, dg = t >> 6;

    float wr[KK];
    #pragma unroll
    for (int k = 0; k < KK; k++) wr[k] = ws_s[x * KK + k];

    int sb[KK];
    #pragma unroll
    for (int k = 0; k < KK; k++) {
        int dx = k % 5 - 2;
        int px = x + dx; px = px < 0 ? 0 : (px > W_-1 ? W_-1 : px);
        sb[k] = (k / 5) * HW_ + px;
    }

    const int d0 = dg * 16;
    float* ob = out + (size_t)n * CHW + y * W_ + x;
    for (int d = d0; d < d0 + 16; d++) {
        const int off = d * 64;
        float p[KK];
        #pragma unroll
        for (int k = 0; k < KK; k++) p[k] = pm_s[sb[k] + off];
        float s0 = 0.f, s1 = 0.f, s2 = 0.f, s3 = 0.f;
        #pragma unroll
        for (int k = 0; k < 24; k += 4) {
            s0 = fmaf(wr[k+0], p[k+0], s0);
            s1 = fmaf(wr[k+1], p[k+1], s1);
            s2 = fmaf(wr[k+2], p[k+2], s2);
            s3 = fmaf(wr[k+3], p[k+3], s3);
        }
        s0 = fmaf(wr[24], p[24], s0);
        ob[(size_t)d * HW_] = (s0 + s1) + (s2 + s3);
    }
}

extern "C" void kernel_launch(void* const* d_in, const int* in_sizes, int n_in,
                              void* d_out, int out_size) {
    const float* cur  = (const float*)d_in[0];
    const float* prev = (const float*)d_in[1];
    const float* pm   = (const float*)d_in[2];
    float* out = (float*)d_out;
    (void)in_sizes; (void)n_in; (void)out_size;

    cudaFuncSetAttribute(weights_kernel, cudaFuncAttributeMaxDynamicSharedMemorySize, 6 * HW_ * 4);
    cudaFuncSetAttribute(output_kernel,  cudaFuncAttributeMaxDynamicSharedMemorySize, (5 * HW_ + W_ * KK) * 4);

    zero_cnt_kernel<<<1, 32>>>();
    count_kernel<<<dim3(64, 2, N_), 256>>>(cur, prev);
    finalize_kernel<<<1, 32>>>();
    weights_kernel<<<dim3(H_, N_), 512, 6 * HW_ * 4>>>(cur, prev);
    output_kernel<<<dim3(H_, N_), 256, (5 * HW_ + W_ * KK) * 4>>>(pm, out);
}

// round 9
// speedup vs baseline: 1.7198x; 1.7198x over previous
#include <cuda_runtime.h>

#define N_   8
#define D_   64
#define H_   64
#define W_   64
#define HW_  4096
#define CHW  (D_*HW_)   /* 262144 */
#define KK   25
#define PW   72          /* padded smem row width: 4 | 64 | 4 */

// Scratch (static __device__ allocation — allowed)
__device__ int   g_cnt[2][N_];
__device__ float g_inv[N_];

__global__ void zero_cnt_kernel() {
    int t = threadIdx.x;
    if (t < 2*N_) ((int*)g_cnt)[t] = 0;
}

__global__ void count_kernel(const float* __restrict__ cur, const float* __restrict__ prev) {
    int arr = blockIdx.y;
    int n   = blockIdx.z;
    const float4* p = (const float4*)((arr == 0 ? cur : prev) + (size_t)n * CHW);
    const int nv = CHW / 4;
    int cnt = 0;
    for (int i = blockIdx.x * blockDim.x + threadIdx.x; i < nv; i += gridDim.x * blockDim.x) {
        float4 v = p[i];
        cnt += (v.x != 0.f) + (v.y != 0.f) + (v.z != 0.f) + (v.w != 0.f);
    }
    #pragma unroll
    for (int o = 16; o; o >>= 1) cnt += __shfl_xor_sync(0xffffffffu, cnt, o);
    __shared__ int ws[8];
    int lane = threadIdx.x & 31, wid = threadIdx.x >> 5;
    if (lane == 0) ws[wid] = cnt;
    __syncthreads();
    if (wid == 0) {
        int c = (lane < (int)(blockDim.x >> 5)) ? ws[lane] : 0;
        #pragma unroll
        for (int o = 4; o; o >>= 1) c += __shfl_xor_sync(0xffffffffu, c, o);
        if (lane == 0) atomicAdd(&g_cnt[arr][n], c);
    }
}

__global__ void finalize_kernel() {
    int t = threadIdx.x;
    if (t < N_) {
        float a = (float)g_cnt[0][t] + 1e-8f;
        float b = (float)g_cnt[1][t] + 1e-8f;
        g_inv[t] = 1.0f / (a * b);
    }
}

// Fully fused: one CTA per (row y, batch n), 160 threads = (g:16, r:5, ds:2).
//   smem: cur region [4096 fl] + padded prev region [5*64*72 fl].
//   Phase A: 25-tap affinity dot-products (vector LDS.128, zero-padded halo).
//   Phase B: relu/mass/normalize -> ws[64][25] (overlaid on cur region).
//   Phase C: prev region refilled with prev_mem; weighted 25-tap gather.
__global__ __launch_bounds__(160) void fused_kernel(const float* __restrict__ cur,
                                                    const float* __restrict__ prev,
                                                    const float* __restrict__ pm,
                                                    float* __restrict__ out) {
    extern __shared__ float sm[];
    float* cur_s  = sm;            // [64 d][64 x]
    float* prev_s = sm + 4096;     // [(r*64+d)][72]  (4-col zero pads each side)
    // overlays (regions dead when these go live):
    float* partial = prev_s;       // [2 ds][5 r][16 g][20]  = 3200 fl  (phase A->B)
    float* ws_s    = sm;           // [64 x][25]            = 1600 fl  (phase B->C)
    float* psum    = sm + 1600;    // [5 r][2 ds][16 g][4 j][2 dd] = 1280 fl (phase C)

    const int y = blockIdx.x, n = blockIdx.y;
    const int t = threadIdx.x;
    const int g  = t & 15;
    const int r  = (t >> 4) % 5;
    const int ds = t / 80;
    const float* curb  = cur  + (size_t)n * CHW;
    const float* prevb = prev + (size_t)n * CHW;
    const float* pmb   = pm   + (size_t)n * CHW;

    // ---- zero padded prev region; fill cur region ----
    for (int i = t; i < 5 * 64 * PW / 4; i += 160)
        ((float4*)prev_s)[i] = make_float4(0.f, 0.f, 0.f, 0.f);
    for (int i = t; i < 1024; i += 160) {
        int d = i >> 4, x4 = i & 15;
        *(float4*)(cur_s + d * 64 + 4 * x4) =
            *(const float4*)(curb + d * HW_ + y * W_ + 4 * x4);
    }
    __syncthreads();

    // ---- fill prev interiors (valid rows only; invalid rows stay zero) ----
    for (int i = t; i < 5 * 1024; i += 160) {
        int rr = i >> 10, rem = i & 1023;
        int d = rem >> 4, x4 = rem & 15;
        int yy = y - 2 + rr;
        if (yy >= 0 && yy < H_)
            *(float4*)(prev_s + (rr * 64 + d) * PW + 4 + 4 * x4) =
                *(const float4*)(prevb + d * HW_ + yy * W_ + 4 * x4);
    }
    __syncthreads();

    // ---- Phase A: affinity partial dots. thread=(g,r,ds); 20 accs ----
    {
        const float* prow = prev_s + (r * 64) * PW + 4 * g;
        const float* crow = cur_s + 4 * g;
        float acc[20];
        #pragma unroll
        for (int i = 0; i < 20; i++) acc[i] = 0.f;
        const int d0 = ds * 32;
        #pragma unroll 4
        for (int d = d0; d < d0 + 32; d++) {
            float4 c4 = *(const float4*)(crow + d * 64);
            float4 a  = *(const float4*)(prow + d * PW);
            float4 b  = *(const float4*)(prow + d * PW + 4);
            float4 e  = *(const float4*)(prow + d * PW + 8);
            float v[12] = {a.x,a.y,a.z,a.w, b.x,b.y,b.z,b.w, e.x,e.y,e.z,e.w};
            float c[4]  = {c4.x, c4.y, c4.z, c4.w};
            #pragma unroll
            for (int j = 0; j < 4; j++)
                #pragma unroll
                for (int dxi = 0; dxi < 5; dxi++)
                    acc[j*5+dxi] = fmaf(c[j], v[j + dxi + 2], acc[j*5+dxi]);
        }
        __syncthreads();   // prev data consumed; partial overlay goes live
        float* pp = partial + ((ds * 5 + r) * 16 + g) * 20;
        #pragma unroll
        for (int i = 0; i < 20; i++) pp[i] = acc[i];
    }
    __syncthreads();

    // ---- Phase B: relu, mass, normalize -> ws[64][25] ----
    if (t < 64) {
        const int x = t, gg = x >> 2, j = x & 3;
        float coef[KK];
        float m = 0.f;
        #pragma unroll
        for (int rr = 0; rr < 5; rr++)
            #pragma unroll
            for (int dxi = 0; dxi < 5; dxi++) {
                float s = partial[((0 + rr) * 16 + gg) * 20 + j*5 + dxi]
                        + partial[((5 + rr) * 16 + gg) * 20 + j*5 + dxi];
                s = fmaxf(s, 0.f);
                coef[rr*5 + dxi] = s;
                m += s;
            }
        const bool  zero = fabsf(m * g_inv[n]) < 1e-7f;
        const float invm = zero ? 0.f : 1.0f / m;
        #pragma unroll
        for (int k = 0; k < KK; k++)
            ws_s[x * KK + k] = zero ? (k == 12 ? 1.0f : 0.0f) : coef[k] * invm;
    }
    __syncthreads();

    // ---- Phase C fill: prev_mem into padded region (pads/invalid rows stay 0) ----
    for (int i = t; i < 5 * 1024; i += 160) {
        int rr = i >> 10, rem = i & 1023;
        int d = rem >> 4, x4 = rem & 15;
        int yy = y - 2 + rr;
        if (yy >= 0 && yy < H_)
            *(float4*)(prev_s + (rr * 64 + d) * PW + 4 + 4 * x4) =
                *(const float4*)(pmb + d * HW_ + yy * W_ + 4 * x4);
    }
    __syncthreads();

    // ---- Phase C: weighted gather. thread=(g,r,ds), 2-d chunks + smem reduce ----
    float wreg[20];
    #pragma unroll
    for (int j = 0; j < 4; j++)
        #pragma unroll
        for (int dxi = 0; dxi < 5; dxi++)
            wreg[j*5+dxi] = ws_s[(4*g + j) * KK + r*5 + dxi];

    const float* prow = prev_s + (r * 64) * PW + 4 * g;
    const int xr = t & 63, dh = t >> 6;     // reader role (t < 128)
    float* ob = out + (size_t)n * CHW + y * W_ + xr;

    for (int ch = 0; ch < 16; ch++) {
        const int dbase = ds * 32 + ch * 2;
        float po[8];
        #pragma unroll
        for (int i = 0; i < 8; i++) po[i] = 0.f;
        #pragma unroll
        for (int dd = 0; dd < 2; dd++) {
            int d = dbase + dd;
            float4 a = *(const float4*)(prow + d * PW);
            float4 b = *(const float4*)(prow + d * PW + 4);
            float4 e = *(const float4*)(prow + d * PW + 8);
            float v[12] = {a.x,a.y,a.z,a.w, b.x,b.y,b.z,b.w, e.x,e.y,e.z,e.w};
            #pragma unroll
            for (int j = 0; j < 4; j++)
                #pragma unroll
                for (int dxi = 0; dxi < 5; dxi++)
                    po[j*2+dd] = fmaf(wreg[j*5+dxi], v[j + dxi + 2], po[j*2+dd]);
        }
        {
            float* pp = psum + ((r * 2 + ds) * 16 + g) * 8;
            #pragma unroll
            for (int i = 0; i < 8; i++) pp[i] = po[i];
        }
        __syncthreads();
        if (t < 128) {
            #pragma unroll
            for (int dd = 0; dd < 2; dd++) {
                int d = dh * 32 + ch * 2 + dd;
                float s = 0.f;
                #pragma unroll
                for (int rr = 0; rr < 5; rr++)
                    s += psum[((rr * 2 + dh) * 16 + (xr >> 2)) * 8 + (xr & 3) * 2 + dd];
                ob[(size_t)d * HW_] = s;
            }
        }
        __syncthreads();
    }
}

extern "C" void kernel_launch(void* const* d_in, const int* in_sizes, int n_in,
                              void* d_out, int out_size) {
    const float* cur  = (const float*)d_in[0];
    const float* prev = (const float*)d_in[1];
    const float* pm   = (const float*)d_in[2];
    float* out = (float*)d_out;
    (void)in_sizes; (void)n_in; (void)out_size;

    const int smem = (4096 + 5 * 64 * PW) * 4;   // 108,544 B
    cudaFuncSetAttribute(fused_kernel, cudaFuncAttributeMaxDynamicSharedMemorySize, smem);

    zero_cnt_kernel<<<1, 32>>>();
    count_kernel<<<dim3(64, 2, N_), 256>>>(cur, prev);
    finalize_kernel<<<1, 32>>>();
    fused_kernel<<<dim3(H_, N_), 160, smem>>>(cur, prev, pm, out);
}